// round 2
// baseline (speedup 1.0000x reference)
#include <cuda_runtime.h>
#include <math.h>

#define BB   128
#define DVC  2048
#define SP   196
#define DQ   2048
#define DA   1200
#define NG   4
#define DHG  512
#define DH   2048
#define NANS 3000
#define MTOT (BB*SP)   // 25088

// ---------------- scratch (static device globals; no allocation) ----------------
__device__ float g_xq_att[BB*DA];          // tanh(q @ Wq_att + b)   [128,1200]
__device__ float g_xqf[BB*DH];             // tanh(q @ Wqf + b)      [128,2048]
__device__ float g_xatt[MTOT*DA];          // tanh(tanh(xv)*xq)      [25088,1200] ~120MB
__device__ float g_scores[MTOT*NG];        // [25088,4]
__device__ float g_att[BB*NG*SP];          // softmaxed, [B,G,S]
__device__ float g_vatt[BB*NG*DVC];        // pooled,    [B,G,DV]
__device__ float g_x[BB*DH];               // tanh(xv*xq) [128,2048]

// ---------------- big fused GEMM: x_att = tanh(tanh(v^T @ Wv + bv) * xq_att) ----
// A: logical [25088, 2048], A[m,k] = v[b, k, s] with b=m/196, s=m%196
// B: Wv_att [2048, 1200]
// tiles: BM=128, BN=128, BK=16, 256 threads, 8x8 micro
__global__ __launch_bounds__(256) void big_gemm_kernel(
    const float* __restrict__ v, const float* __restrict__ Wv,
    const float* __restrict__ bv)
{
    __shared__ float As[16][128];
    __shared__ float Bs[16][128];
    const int tid = threadIdx.x;
    const int bm = blockIdx.y, bn = blockIdx.x;

    // A-load mapping: 128 threads along m (coalesced over s), 2 k-rows per pass
    const int lm  = tid & 127;
    const int lk  = tid >> 7;            // 0..1
    const int m_g = bm * 128 + lm;
    const int bb  = m_g / SP;
    const int ss  = m_g - bb * SP;
    const float* a_base = v + (size_t)bb * DVC * SP + ss;

    // B-load mapping
    const int ln  = tid & 127;
    const int lkb = tid >> 7;
    const int n_g = bn * 128 + ln;
    const bool nv = (n_g < DA);

    const int tr = tid >> 4;   // 0..15 -> rows tr*8..tr*8+7
    const int tc = tid & 15;   // 0..15 -> cols tc*8..tc*8+7

    float acc[8][8];
    #pragma unroll
    for (int i = 0; i < 8; i++)
        #pragma unroll
        for (int j = 0; j < 8; j++) acc[i][j] = 0.f;

    for (int k0 = 0; k0 < DVC; k0 += 16) {
        #pragma unroll
        for (int i = 0; i < 8; i++) {
            int kk = lk + 2 * i;
            As[kk][lm] = __ldg(&a_base[(size_t)(k0 + kk) * SP]);
            int kb = lkb + 2 * i;
            Bs[kb][ln] = nv ? __ldg(&Wv[(size_t)(k0 + kb) * DA + n_g]) : 0.f;
        }
        __syncthreads();
        #pragma unroll
        for (int kk = 0; kk < 16; kk++) {
            float4 a0 = *reinterpret_cast<const float4*>(&As[kk][tr * 8]);
            float4 a1 = *reinterpret_cast<const float4*>(&As[kk][tr * 8 + 4]);
            float4 b0 = *reinterpret_cast<const float4*>(&Bs[kk][tc * 8]);
            float4 b1 = *reinterpret_cast<const float4*>(&Bs[kk][tc * 8 + 4]);
            float ar[8] = {a0.x, a0.y, a0.z, a0.w, a1.x, a1.y, a1.z, a1.w};
            float br[8] = {b0.x, b0.y, b0.z, b0.w, b1.x, b1.y, b1.z, b1.w};
            #pragma unroll
            for (int i = 0; i < 8; i++)
                #pragma unroll
                for (int j = 0; j < 8; j++)
                    acc[i][j] = fmaf(ar[i], br[j], acc[i][j]);
        }
        __syncthreads();
    }

    #pragma unroll
    for (int i = 0; i < 8; i++) {
        int m = bm * 128 + tr * 8 + i;
        int b_i = m / SP;
        #pragma unroll
        for (int j = 0; j < 8; j++) {
            int n = bn * 128 + tc * 8 + j;
            if (n < DA) {
                float t1 = tanhf(acc[i][j] + bv[n]);
                float t2 = tanhf(t1 * g_xq_att[b_i * DA + n]);
                g_xatt[(size_t)m * DA + n] = t2;
            }
        }
    }
}

// ---------------- generic small GEMM (M multiple of 32), fused epilogues -------
// EPI 0: C = acc + bias
// EPI 1: C = tanh(acc + bias)
// EPI 2: C = tanh( tanh(acc + bias) * aux[m*ldaux + n] )
template <int EPI>
__global__ __launch_bounds__(256) void gemm_kernel(
    const float* __restrict__ A, int lda,
    const float* __restrict__ Bm, int ldb,
    const float* __restrict__ bias,
    const float* __restrict__ aux, int ldaux,
    float* __restrict__ C, int ldc,
    int M, int N, int K)
{
    __shared__ float As[16][33];   // padded to avoid store bank conflicts
    __shared__ float Bs[16][64];
    const int tid = threadIdx.x;
    const int bm = blockIdx.y, bn = blockIdx.x;
    const int tr = tid >> 4, tc = tid & 15;

    const int ak = tid & 15;       // k within tile
    const int am = tid >> 4;       // m within tile (0..15), +16 second pass
    const int bn_l = tid & 63;
    const int bk   = tid >> 6;     // 0..3, +4 per pass
    const int n_g  = bn * 64 + bn_l;
    const bool nvl = (n_g < N);

    float acc[2][4] = {{0.f,0.f,0.f,0.f},{0.f,0.f,0.f,0.f}};

    for (int k0 = 0; k0 < K; k0 += 16) {
        As[ak][am]      = A[(size_t)(bm * 32 + am)      * lda + k0 + ak];
        As[ak][am + 16] = A[(size_t)(bm * 32 + am + 16) * lda + k0 + ak];
        #pragma unroll
        for (int i = 0; i < 4; i++) {
            int kk = bk + 4 * i;
            Bs[kk][bn_l] = nvl ? Bm[(size_t)(k0 + kk) * ldb + n_g] : 0.f;
        }
        __syncthreads();
        #pragma unroll
        for (int kk = 0; kk < 16; kk++) {
            float a0 = As[kk][tr * 2];
            float a1 = As[kk][tr * 2 + 1];
            float4 b = *reinterpret_cast<const float4*>(&Bs[kk][tc * 4]);
            float br[4] = {b.x, b.y, b.z, b.w};
            #pragma unroll
            for (int j = 0; j < 4; j++) {
                acc[0][j] = fmaf(a0, br[j], acc[0][j]);
                acc[1][j] = fmaf(a1, br[j], acc[1][j]);
            }
        }
        __syncthreads();
    }

    #pragma unroll
    for (int i = 0; i < 2; i++) {
        int m = bm * 32 + tr * 2 + i;
        #pragma unroll
        for (int j = 0; j < 4; j++) {
            int n = bn * 64 + tc * 4 + j;
            if (n < N) {
                float r = acc[i][j] + bias[n];
                if (EPI == 0) {
                    C[(size_t)m * ldc + n] = r;
                } else if (EPI == 1) {
                    C[(size_t)m * ldc + n] = tanhf(r);
                } else {
                    float t = tanhf(r);
                    C[(size_t)m * ldc + n] = tanhf(t * aux[(size_t)m * ldaux + n]);
                }
            }
        }
    }
}

// ---------------- scores = x_att @ Wa + ba  (skinny, memory-bound) -------------
__global__ __launch_bounds__(256) void scores_kernel(
    const float* __restrict__ Wa, const float* __restrict__ ba)
{
    const int m = blockIdx.x;
    const int tid = threadIdx.x;
    const float* row = g_xatt + (size_t)m * DA;
    float a[4] = {0.f, 0.f, 0.f, 0.f};
    for (int d = tid; d < DA; d += 256) {
        float x = row[d];
        float4 w = *reinterpret_cast<const float4*>(&Wa[d * 4]);
        a[0] = fmaf(x, w.x, a[0]);
        a[1] = fmaf(x, w.y, a[1]);
        a[2] = fmaf(x, w.z, a[2]);
        a[3] = fmaf(x, w.w, a[3]);
    }
    #pragma unroll
    for (int off = 16; off > 0; off >>= 1)
        #pragma unroll
        for (int g = 0; g < 4; g++)
            a[g] += __shfl_down_sync(0xffffffffu, a[g], off);

    __shared__ float red[8][4];
    const int lane = tid & 31, w = tid >> 5;
    if (lane == 0) { red[w][0] = a[0]; red[w][1] = a[1]; red[w][2] = a[2]; red[w][3] = a[3]; }
    __syncthreads();
    if (tid < 4) {
        float s = ba[tid];
        #pragma unroll
        for (int ww = 0; ww < 8; ww++) s += red[ww][tid];
        g_scores[(size_t)m * NG + tid] = s;
    }
}

// ---------------- softmax over spatial S, per (b,g) ----------------------------
__global__ __launch_bounds__(256) void softmax_kernel()
{
    const int bg = blockIdx.x;       // b*4+g
    const int b = bg >> 2, g = bg & 3;
    const int tid = threadIdx.x;
    const int lane = tid & 31, w = tid >> 5;
    __shared__ float sh[8];

    float val = -1e30f;
    if (tid < SP) val = g_scores[((size_t)b * SP + tid) * NG + g];

    float v = val;
    #pragma unroll
    for (int off = 16; off > 0; off >>= 1)
        v = fmaxf(v, __shfl_xor_sync(0xffffffffu, v, off));
    if (lane == 0) sh[w] = v;
    __syncthreads();
    float mx = sh[0];
    #pragma unroll
    for (int i = 1; i < 8; i++) mx = fmaxf(mx, sh[i]);

    float e = (tid < SP) ? expf(val - mx) : 0.f;
    __syncthreads();
    float s = e;
    #pragma unroll
    for (int off = 16; off > 0; off >>= 1)
        s += __shfl_xor_sync(0xffffffffu, s, off);
    if (lane == 0) sh[w] = s;
    __syncthreads();
    float tot = 0.f;
    #pragma unroll
    for (int i = 0; i < 8; i++) tot += sh[i];

    if (tid < SP) g_att[(size_t)bg * SP + tid] = e / tot;
}

// ---------------- attention pooling: v_att[b,g,c] = sum_s att[b,g,s]*v[b,c,s] --
__global__ __launch_bounds__(128) void pool_kernel(const float* __restrict__ v)
{
    __shared__ float sv[32][197];   // 197 stride -> conflict-free (gcd(5,32)=1)
    __shared__ float sa[NG][SP];
    const int b = blockIdx.x;
    const int c0 = blockIdx.y * 32;
    const int tid = threadIdx.x;

    for (int i = tid; i < NG * SP; i += 128)
        sa[i / SP][i % SP] = g_att[(size_t)b * NG * SP + i];
    const float* vb = v + (size_t)b * DVC * SP + (size_t)c0 * SP;
    for (int i = tid; i < 32 * SP; i += 128)
        sv[i / SP][i % SP] = vb[i];
    __syncthreads();

    const int g = tid >> 5, ci = tid & 31;
    float acc = 0.f;
    #pragma unroll 4
    for (int s = 0; s < SP; s++)
        acc = fmaf(sa[g][s], sv[ci][s], acc);
    g_vatt[(size_t)b * NG * DVC + (size_t)g * DVC + c0 + ci] = acc;
}

// ---------------- launch ---------------------------------------------------------
extern "C" void kernel_launch(void* const* d_in, const int* in_sizes, int n_in,
                              void* d_out, int out_size)
{
    const float* input_v = (const float*)d_in[0];
    const float* x_q     = (const float*)d_in[1];
    const float* Wv_att  = (const float*)d_in[2];
    const float* bv_att  = (const float*)d_in[3];
    const float* Wq_att  = (const float*)d_in[4];
    const float* bq_att  = (const float*)d_in[5];
    const float* Wa      = (const float*)d_in[6];
    const float* ba      = (const float*)d_in[7];
    const float* Wf      = (const float*)d_in[8];
    const float* bf      = (const float*)d_in[9];
    const float* Wqf     = (const float*)d_in[10];
    const float* bqf     = (const float*)d_in[11];
    const float* Wc      = (const float*)d_in[12];
    const float* bc      = (const float*)d_in[13];
    float* out = (float*)d_out;

    float *p_xq_att, *p_xqf, *p_vatt, *p_x;
    cudaGetSymbolAddress((void**)&p_xq_att, g_xq_att);
    cudaGetSymbolAddress((void**)&p_xqf,    g_xqf);
    cudaGetSymbolAddress((void**)&p_vatt,   g_vatt);
    cudaGetSymbolAddress((void**)&p_x,      g_x);

    // 1) q projections
    gemm_kernel<1><<<dim3((DA + 63) / 64, BB / 32), 256>>>(
        x_q, DQ, Wq_att, DA, bq_att, nullptr, 0, p_xq_att, DA, BB, DA, DQ);
    gemm_kernel<1><<<dim3(DH / 64, BB / 32), 256>>>(
        x_q, DQ, Wqf, DH, bqf, nullptr, 0, p_xqf, DH, BB, DH, DQ);

    // 2) big fused GEMM -> g_xatt
    big_gemm_kernel<<<dim3((DA + 127) / 128, MTOT / 128), 256>>>(input_v, Wv_att, bv_att);

    // 3) scores
    scores_kernel<<<MTOT, 256>>>(Wa, ba);

    // 4) softmax over S
    softmax_kernel<<<BB * NG, 256>>>();

    // 5) attention pooling
    pool_kernel<<<dim3(BB, DVC / 32), 128>>>(input_v);

    // 6) per-glimpse fusion (4 launches), fused MLB epilogue -> g_x
    for (int g = 0; g < NG; g++) {
        gemm_kernel<2><<<dim3(DHG / 64, BB / 32), 256>>>(
            p_vatt + g * DVC, NG * DVC,
            Wf + (size_t)g * DVC * DHG, DHG,
            bf + g * DHG,
            p_xqf + g * DHG, DH,
            p_x + g * DHG, DH,
            BB, DHG, DVC);
    }

    // 7) classifier -> out
    gemm_kernel<0><<<dim3((NANS + 63) / 64, BB / 32), 256>>>(
        p_x, DH, Wc, NANS, bc, nullptr, 0, out, NANS, BB, NANS, DH);
}

// round 3
// speedup vs baseline: 1.7861x; 1.7861x over previous
#include <cuda_runtime.h>
#include <cuda_bf16.h>
#include <math.h>
#include <stdint.h>

#define BB   128
#define DVC  2048
#define SP   196
#define DQ   2048
#define DA   1200
#define NG   4
#define DHG  512
#define DH   2048
#define NANS 3000
#define MTOT (BB*SP)   // 25088
#define NPAD 1280      // DA padded to multiple of 128 for the mma GEMM

// ---------------- scratch (static device globals; no allocation) ----------------
__device__ float g_xq_att[BB*DA];          // tanh(q @ Wq_att + b)   [128,1200]
__device__ float g_xqf[BB*DH];             // tanh(q @ Wqf + b)      [128,2048]
__device__ float g_xatt[(size_t)MTOT*DA];  // tanh(tanh(xv)*xq)      [25088,1200]
__device__ float g_scores[MTOT*NG];        // [25088,4]
__device__ float g_att[BB*NG*SP];          // softmaxed, [B,G,S]
__device__ float g_vatt[BB*NG*DVC];        // pooled,    [B,G,DV]
__device__ float g_x[BB*DH];               // tanh(xv*xq) [128,2048]

// bf16 split operands for the big GEMM
__device__ __nv_bfloat16 g_Ahi[(size_t)MTOT*DVC];  // [m][k] row-major
__device__ __nv_bfloat16 g_Alo[(size_t)MTOT*DVC];
__device__ __nv_bfloat16 g_Bhi[(size_t)DVC*NPAD];  // [k][n], zero-padded n>=1200
__device__ __nv_bfloat16 g_Blo[(size_t)DVC*NPAD];

// ================= conversion kernels =================
// A[m][k] = v[b][k][s] with m = b*196+s  (transpose per batch) -> hi/lo bf16
__global__ __launch_bounds__(256) void convA_kernel(const float* __restrict__ v)
{
    __shared__ float t[32][33];
    const int b  = blockIdx.z;
    const int k0 = blockIdx.x * 32;
    const int s0 = blockIdx.y * 32;
    const int tx = threadIdx.x, ty = threadIdx.y;  // 32 x 8

    #pragma unroll
    for (int i = ty; i < 32; i += 8) {
        int s = s0 + tx, k = k0 + i;
        t[i][tx] = (s < SP) ? v[((size_t)b * DVC + k) * SP + s] : 0.f;
    }
    __syncthreads();
    #pragma unroll
    for (int i = ty; i < 32; i += 8) {
        int s = s0 + i;
        if (s >= SP) continue;
        int k = k0 + tx;
        float x = t[tx][i];
        __nv_bfloat16 h = __float2bfloat16_rn(x);
        float lo = x - __bfloat162float(h);
        size_t idx = ((size_t)(b * SP + s)) * DVC + k;
        g_Ahi[idx] = h;
        g_Alo[idx] = __float2bfloat16_rn(lo);
    }
}

__global__ __launch_bounds__(256) void convB_kernel(const float* __restrict__ W)
{
    const int k = blockIdx.y;
    const int n = blockIdx.x * 256 + threadIdx.x;
    if (n >= NPAD) return;
    float x = (n < DA) ? W[(size_t)k * DA + n] : 0.f;
    __nv_bfloat16 h = __float2bfloat16_rn(x);
    float lo = x - __bfloat162float(h);
    size_t idx = (size_t)k * NPAD + n;
    g_Bhi[idx] = h;
    g_Blo[idx] = __float2bfloat16_rn(lo);
}

// ================= big GEMM via mma.sync bf16x3 =================
// C[m][n] = sum_k A[m][k]*B[k][n]  ~ Ahi*Bhi + Ahi*Blo + Alo*Bhi (fp32 accum)
// epilogue: g_xatt = tanh( tanh(C + bv) * g_xq_att[b] )
// tiles: BM=128, BN=128, BK=32, 256 thr (8 warps: 4(M) x 2(N)), STAGES=4

#define STAGES 4
#define STAGE_BYTES 32768   // Ahi 8K | Alo 8K | Bhi 8K | Blo 8K

#define CP_ASYNC16(dst, src) \
    asm volatile("cp.async.cg.shared.global [%0], [%1], 16;\n" :: "r"(dst), "l"(src))
#define CP_COMMIT() asm volatile("cp.async.commit_group;\n")
#define CP_WAIT(n)  asm volatile("cp.async.wait_group %0;\n" :: "n"(n))

#define LDSM4(R, addr) \
    asm volatile("ldmatrix.sync.aligned.m8n8.x4.shared.b16 {%0,%1,%2,%3}, [%4];" \
        : "=r"((R)[0]), "=r"((R)[1]), "=r"((R)[2]), "=r"((R)[3]) : "r"(addr))
#define LDSM4T(R, addr) \
    asm volatile("ldmatrix.sync.aligned.m8n8.x4.trans.shared.b16 {%0,%1,%2,%3}, [%4];" \
        : "=r"((R)[0]), "=r"((R)[1]), "=r"((R)[2]), "=r"((R)[3]) : "r"(addr))

#define MMA16816(D, A, b0, b1) \
    asm volatile("mma.sync.aligned.m16n8k16.row.col.f32.bf16.bf16.f32 " \
        "{%0,%1,%2,%3}, {%4,%5,%6,%7}, {%8,%9}, {%0,%1,%2,%3};" \
        : "+f"((D)[0]), "+f"((D)[1]), "+f"((D)[2]), "+f"((D)[3]) \
        : "r"((A)[0]), "r"((A)[1]), "r"((A)[2]), "r"((A)[3]), "r"(b0), "r"(b1))

__global__ __launch_bounds__(256, 1) void mma_gemm_kernel(const float* __restrict__ bv)
{
    extern __shared__ char smem[];
    const uint32_t smem_base = (uint32_t)__cvta_generic_to_shared(smem);

    const int tid   = threadIdx.x;
    const int lane  = tid & 31;
    const int warp  = tid >> 5;
    const int warpM = warp >> 1;    // 0..3 (32 rows each)
    const int warpN = warp & 1;     // 0..1 (64 cols each)
    const int m_blk = blockIdx.y * 128;
    const int n_blk = blockIdx.x * 128;

    // ---- cp.async store mapping (per thread) ----
    const int a_m  = tid >> 1;                 // A row within tile
    const int a_c0 = (tid & 1) * 2;            // first of 2 chunks (8 bf16 each)
    const uint32_t a_sw0 = (uint32_t)((a_c0       ^ ((a_m >> 1) & 3)) << 4);
    const uint32_t a_sw1 = (uint32_t)(((a_c0 + 1) ^ ((a_m >> 1) & 3)) << 4);
    const int b_k  = tid >> 3;                 // B row within tile
    const int b_c0 = (tid & 7) * 2;
    const uint32_t b_sw0 = (uint32_t)((b_c0       ^ (b_k & 7)) << 4);
    const uint32_t b_sw1 = (uint32_t)(((b_c0 + 1) ^ (b_k & 7)) << 4);

    const __nv_bfloat16* srcAhi = g_Ahi + (size_t)(m_blk + a_m) * DVC + a_c0 * 8;
    const __nv_bfloat16* srcAlo = g_Alo + (size_t)(m_blk + a_m) * DVC + a_c0 * 8;
    const __nv_bfloat16* srcBhi = g_Bhi + (size_t)b_k * NPAD + n_blk + b_c0 * 8;
    const __nv_bfloat16* srcBlo = g_Blo + (size_t)b_k * NPAD + n_blk + b_c0 * 8;

    auto issue = [&](int kt) {
        uint32_t st = smem_base + (uint32_t)(kt % STAGES) * STAGE_BYTES;
        const __nv_bfloat16* pa  = srcAhi + kt * 32;
        const __nv_bfloat16* pal = srcAlo + kt * 32;
        uint32_t dA  = st + a_m * 64;
        CP_ASYNC16(dA + a_sw0, pa);
        CP_ASYNC16(dA + a_sw1, pa + 8);
        uint32_t dAl = st + 8192 + a_m * 64;
        CP_ASYNC16(dAl + a_sw0, pal);
        CP_ASYNC16(dAl + a_sw1, pal + 8);
        const __nv_bfloat16* pb  = srcBhi + (size_t)kt * 32 * NPAD;
        const __nv_bfloat16* pbl = srcBlo + (size_t)kt * 32 * NPAD;
        uint32_t dB  = st + 16384 + b_k * 256;
        CP_ASYNC16(dB + b_sw0, pb);
        CP_ASYNC16(dB + b_sw1, pb + 8);
        uint32_t dBl = st + 24576 + b_k * 256;
        CP_ASYNC16(dBl + b_sw0, pbl);
        CP_ASYNC16(dBl + b_sw1, pbl + 8);
    };

    float acc[2][8][4];
    #pragma unroll
    for (int i = 0; i < 2; i++)
        #pragma unroll
        for (int j = 0; j < 8; j++)
            #pragma unroll
            for (int l = 0; l < 4; l++) acc[i][j][l] = 0.f;

    #pragma unroll
    for (int s = 0; s < STAGES - 1; s++) { issue(s); CP_COMMIT(); }

    const int KT = DVC / 32;   // 64
    for (int kt = 0; kt < KT; kt++) {
        CP_WAIT(STAGES - 2);
        __syncthreads();
        uint32_t st = smem_base + (uint32_t)(kt % STAGES) * STAGE_BYTES;

        #pragma unroll
        for (int ks = 0; ks < 2; ks++) {
            uint32_t ahi[2][4], alo[2][4], bhi[4][4], blo[4][4];
            #pragma unroll
            for (int mt = 0; mt < 2; mt++) {
                int row = warpM * 32 + mt * 16 + (lane & 15);
                int lc  = ks * 2 + (lane >> 4);
                uint32_t off = (uint32_t)(row * 64 + ((lc ^ ((row >> 1) & 3)) << 4));
                LDSM4(ahi[mt], st + off);
                LDSM4(alo[mt], st + 8192 + off);
            }
            #pragma unroll
            for (int nt = 0; nt < 4; nt++) {
                int row = ks * 16 + (lane & 15);
                int lc  = warpN * 8 + nt * 2 + (lane >> 4);
                uint32_t off = (uint32_t)(row * 256 + ((lc ^ (row & 7)) << 4));
                LDSM4T(bhi[nt], st + 16384 + off);
                LDSM4T(blo[nt], st + 24576 + off);
            }
            if (ks == 0) {
                int nk = kt + STAGES - 1;
                if (nk < KT) issue(nk);
                CP_COMMIT();
            }
            // 3 products: hi*hi, hi*lo, lo*hi
            #pragma unroll
            for (int p = 0; p < 3; p++) {
                #pragma unroll
                for (int n8 = 0; n8 < 8; n8++) {
                    uint32_t b0, b1;
                    if (p == 1) { b0 = blo[n8 >> 1][(n8 & 1) * 2]; b1 = blo[n8 >> 1][(n8 & 1) * 2 + 1]; }
                    else        { b0 = bhi[n8 >> 1][(n8 & 1) * 2]; b1 = bhi[n8 >> 1][(n8 & 1) * 2 + 1]; }
                    #pragma unroll
                    for (int mt = 0; mt < 2; mt++) {
                        const uint32_t* Af = (p == 2) ? alo[mt] : ahi[mt];
                        MMA16816(acc[mt][n8], Af, b0, b1);
                    }
                }
            }
        }
    }

    // ---- fused epilogue ----
    const int gq  = lane >> 2;
    const int tig = lane & 3;
    #pragma unroll
    for (int mt = 0; mt < 2; mt++) {
        #pragma unroll
        for (int n8 = 0; n8 < 8; n8++) {
            int nbase = n_blk + warpN * 64 + n8 * 8 + tig * 2;
            #pragma unroll
            for (int i = 0; i < 4; i++) {
                int r = m_blk + warpM * 32 + mt * 16 + gq + (i >> 1) * 8;
                int n = nbase + (i & 1);
                if (n < DA) {
                    int bi = r / SP;
                    float x  = acc[mt][n8][i] + bv[n];
                    float t1 = tanhf(x);
                    float t2 = tanhf(t1 * g_xq_att[bi * DA + n]);
                    g_xatt[(size_t)r * DA + n] = t2;
                }
            }
        }
    }
}

// ---------------- generic small GEMM (M multiple of 32), fused epilogues -------
template <int EPI>
__global__ __launch_bounds__(256) void gemm_kernel(
    const float* __restrict__ A, int lda,
    const float* __restrict__ Bm, int ldb,
    const float* __restrict__ bias,
    const float* __restrict__ aux, int ldaux,
    float* __restrict__ C, int ldc,
    int M, int N, int K)
{
    __shared__ float As[16][33];
    __shared__ float Bs[16][64];
    const int tid = threadIdx.x;
    const int bm = blockIdx.y, bn = blockIdx.x;
    const int tr = tid >> 4, tc = tid & 15;

    const int ak = tid & 15;
    const int am = tid >> 4;
    const int bn_l = tid & 63;
    const int bk   = tid >> 6;
    const int n_g  = bn * 64 + bn_l;
    const bool nvl = (n_g < N);

    float acc[2][4] = {{0.f,0.f,0.f,0.f},{0.f,0.f,0.f,0.f}};

    for (int k0 = 0; k0 < K; k0 += 16) {
        As[ak][am]      = A[(size_t)(bm * 32 + am)      * lda + k0 + ak];
        As[ak][am + 16] = A[(size_t)(bm * 32 + am + 16) * lda + k0 + ak];
        #pragma unroll
        for (int i = 0; i < 4; i++) {
            int kk = bk + 4 * i;
            Bs[kk][bn_l] = nvl ? Bm[(size_t)(k0 + kk) * ldb + n_g] : 0.f;
        }
        __syncthreads();
        #pragma unroll
        for (int kk = 0; kk < 16; kk++) {
            float a0 = As[kk][tr * 2];
            float a1 = As[kk][tr * 2 + 1];
            float4 b = *reinterpret_cast<const float4*>(&Bs[kk][tc * 4]);
            float br[4] = {b.x, b.y, b.z, b.w};
            #pragma unroll
            for (int j = 0; j < 4; j++) {
                acc[0][j] = fmaf(a0, br[j], acc[0][j]);
                acc[1][j] = fmaf(a1, br[j], acc[1][j]);
            }
        }
        __syncthreads();
    }

    #pragma unroll
    for (int i = 0; i < 2; i++) {
        int m = bm * 32 + tr * 2 + i;
        #pragma unroll
        for (int j = 0; j < 4; j++) {
            int n = bn * 64 + tc * 4 + j;
            if (n < N) {
                float r = acc[i][j] + bias[n];
                if (EPI == 0) {
                    C[(size_t)m * ldc + n] = r;
                } else if (EPI == 1) {
                    C[(size_t)m * ldc + n] = tanhf(r);
                } else {
                    float t = tanhf(r);
                    C[(size_t)m * ldc + n] = tanhf(t * aux[(size_t)m * ldaux + n]);
                }
            }
        }
    }
}

// ---------------- scores = x_att @ Wa + ba ----------------
__global__ __launch_bounds__(256) void scores_kernel(
    const float* __restrict__ Wa, const float* __restrict__ ba)
{
    const int m = blockIdx.x;
    const int tid = threadIdx.x;
    const float* row = g_xatt + (size_t)m * DA;
    float a[4] = {0.f, 0.f, 0.f, 0.f};
    for (int d = tid; d < DA; d += 256) {
        float x = row[d];
        float4 w = *reinterpret_cast<const float4*>(&Wa[d * 4]);
        a[0] = fmaf(x, w.x, a[0]);
        a[1] = fmaf(x, w.y, a[1]);
        a[2] = fmaf(x, w.z, a[2]);
        a[3] = fmaf(x, w.w, a[3]);
    }
    #pragma unroll
    for (int off = 16; off > 0; off >>= 1)
        #pragma unroll
        for (int g = 0; g < 4; g++)
            a[g] += __shfl_down_sync(0xffffffffu, a[g], off);

    __shared__ float red[8][4];
    const int lane = tid & 31, w = tid >> 5;
    if (lane == 0) { red[w][0] = a[0]; red[w][1] = a[1]; red[w][2] = a[2]; red[w][3] = a[3]; }
    __syncthreads();
    if (tid < 4) {
        float s = ba[tid];
        #pragma unroll
        for (int ww = 0; ww < 8; ww++) s += red[ww][tid];
        g_scores[(size_t)m * NG + tid] = s;
    }
}

// ---------------- softmax over spatial S, per (b,g) ----------------
__global__ __launch_bounds__(256) void softmax_kernel()
{
    const int bg = blockIdx.x;
    const int b = bg >> 2, g = bg & 3;
    const int tid = threadIdx.x;
    const int lane = tid & 31, w = tid >> 5;
    __shared__ float sh[8];

    float val = -1e30f;
    if (tid < SP) val = g_scores[((size_t)b * SP + tid) * NG + g];

    float v = val;
    #pragma unroll
    for (int off = 16; off > 0; off >>= 1)
        v = fmaxf(v, __shfl_xor_sync(0xffffffffu, v, off));
    if (lane == 0) sh[w] = v;
    __syncthreads();
    float mx = sh[0];
    #pragma unroll
    for (int i = 1; i < 8; i++) mx = fmaxf(mx, sh[i]);

    float e = (tid < SP) ? expf(val - mx) : 0.f;
    __syncthreads();
    float s = e;
    #pragma unroll
    for (int off = 16; off > 0; off >>= 1)
        s += __shfl_xor_sync(0xffffffffu, s, off);
    if (lane == 0) sh[w] = s;
    __syncthreads();
    float tot = 0.f;
    #pragma unroll
    for (int i = 0; i < 8; i++) tot += sh[i];

    if (tid < SP) g_att[(size_t)bg * SP + tid] = e / tot;
}

// ---------------- attention pooling ----------------
__global__ __launch_bounds__(128) void pool_kernel(const float* __restrict__ v)
{
    __shared__ float sv[32][197];
    __shared__ float sa[NG][SP];
    const int b = blockIdx.x;
    const int c0 = blockIdx.y * 32;
    const int tid = threadIdx.x;

    for (int i = tid; i < NG * SP; i += 128)
        sa[i / SP][i % SP] = g_att[(size_t)b * NG * SP + i];
    const float* vb = v + (size_t)b * DVC * SP + (size_t)c0 * SP;
    for (int i = tid; i < 32 * SP; i += 128)
        sv[i / SP][i % SP] = vb[i];
    __syncthreads();

    const int g = tid >> 5, ci = tid & 31;
    float acc = 0.f;
    #pragma unroll 4
    for (int s = 0; s < SP; s++)
        acc = fmaf(sa[g][s], sv[ci][s], acc);
    g_vatt[(size_t)b * NG * DVC + (size_t)g * DVC + c0 + ci] = acc;
}

// ---------------- launch ----------------
extern "C" void kernel_launch(void* const* d_in, const int* in_sizes, int n_in,
                              void* d_out, int out_size)
{
    const float* input_v = (const float*)d_in[0];
    const float* x_q     = (const float*)d_in[1];
    const float* Wv_att  = (const float*)d_in[2];
    const float* bv_att  = (const float*)d_in[3];
    const float* Wq_att  = (const float*)d_in[4];
    const float* bq_att  = (const float*)d_in[5];
    const float* Wa      = (const float*)d_in[6];
    const float* ba      = (const float*)d_in[7];
    const float* Wf      = (const float*)d_in[8];
    const float* bf      = (const float*)d_in[9];
    const float* Wqf     = (const float*)d_in[10];
    const float* bqf     = (const float*)d_in[11];
    const float* Wc      = (const float*)d_in[12];
    const float* bc      = (const float*)d_in[13];
    float* out = (float*)d_out;

    float *p_xq_att, *p_xqf, *p_vatt, *p_x;
    cudaGetSymbolAddress((void**)&p_xq_att, g_xq_att);
    cudaGetSymbolAddress((void**)&p_xqf,    g_xqf);
    cudaGetSymbolAddress((void**)&p_vatt,   g_vatt);
    cudaGetSymbolAddress((void**)&p_x,      g_x);

    cudaFuncSetAttribute(mma_gemm_kernel,
                         cudaFuncAttributeMaxDynamicSharedMemorySize,
                         STAGES * STAGE_BYTES);

    // 0) bf16 split conversions for the big GEMM
    convB_kernel<<<dim3(NPAD / 256, DVC), 256>>>(Wv_att);
    convA_kernel<<<dim3(DVC / 32, (SP + 31) / 32, BB), dim3(32, 8)>>>(input_v);

    // 1) q projections (epilogue of big GEMM reads g_xq_att)
    gemm_kernel<1><<<dim3((DA + 63) / 64, BB / 32), 256>>>(
        x_q, DQ, Wq_att, DA, bq_att, nullptr, 0, p_xq_att, DA, BB, DA, DQ);
    gemm_kernel<1><<<dim3(DH / 64, BB / 32), 256>>>(
        x_q, DQ, Wqf, DH, bqf, nullptr, 0, p_xqf, DH, BB, DH, DQ);

    // 2) big fused GEMM (bf16x3 tensor cores) -> g_xatt
    mma_gemm_kernel<<<dim3(NPAD / 128, MTOT / 128), 256, STAGES * STAGE_BYTES>>>(bv_att);

    // 3) scores
    scores_kernel<<<MTOT, 256>>>(Wa, ba);

    // 4) softmax over S
    softmax_kernel<<<BB * NG, 256>>>();

    // 5) attention pooling
    pool_kernel<<<dim3(BB, DVC / 32), 128>>>(input_v);

    // 6) per-glimpse fusion with fused MLB epilogue -> g_x
    for (int g = 0; g < NG; g++) {
        gemm_kernel<2><<<dim3(DHG / 64, BB / 32), 256>>>(
            p_vatt + g * DVC, NG * DVC,
            Wf + (size_t)g * DVC * DHG, DHG,
            bf + g * DHG,
            p_xqf + g * DHG, DH,
            p_x + g * DHG, DH,
            BB, DHG, DVC);
    }

    // 7) classifier -> out
    gemm_kernel<0><<<dim3((NANS + 63) / 64, BB / 32), 256>>>(
        p_x, DH, Wc, NANS, bc, nullptr, 0, out, NANS, BB, NANS, DH);
}

// round 5
// speedup vs baseline: 3.1590x; 1.7687x over previous
#include <cuda_runtime.h>
#include <cuda_fp16.h>
#include <math.h>
#include <stdint.h>

#define BB   128
#define DVC  2048
#define SP   196
#define DQ   2048
#define DA   1200
#define NG   4
#define DHG  512
#define DH   2048
#define NANS 3000
#define MTOT (BB*SP)     // 25088
#define NPAD 1280
#define NBLK (NPAD/128)  // 10 n-blocks

// ---------------- scratch (static device globals) ----------------
__device__ float g_xq_att[BB*DA];
__device__ float g_xqf[BB*DH];
__device__ float g_att[BB*NG*SP];
__device__ float g_vatt[BB*NG*DVC];
__device__ float g_x[BB*DH];
__device__ float g_spart[NBLK*MTOT*NG];   // per-n-block partial scores
__device__ float g_part[8*128*3008];      // split-K partials (reused)

__device__ __half g_Ahi[(size_t)MTOT*DVC];   // [m][k]
__device__ __half g_Alo[(size_t)MTOT*DVC];
__device__ __half g_Bh [(size_t)DVC*NPAD];   // [k][n], zero padded to NPAD

// ---------------- PTX helpers ----------------
#define CP_ASYNC16(dst, src) \
    asm volatile("cp.async.cg.shared.global [%0], [%1], 16;\n" :: "r"(dst), "l"(src))
#define CP_COMMIT() asm volatile("cp.async.commit_group;\n")
#define CP_WAIT(n)  asm volatile("cp.async.wait_group %0;\n" :: "n"(n))

#define LDSM4(R, addr) \
    asm volatile("ldmatrix.sync.aligned.m8n8.x4.shared.b16 {%0,%1,%2,%3}, [%4];" \
        : "=r"((R)[0]), "=r"((R)[1]), "=r"((R)[2]), "=r"((R)[3]) : "r"(addr))
#define LDSM4T(R, addr) \
    asm volatile("ldmatrix.sync.aligned.m8n8.x4.trans.shared.b16 {%0,%1,%2,%3}, [%4];" \
        : "=r"((R)[0]), "=r"((R)[1]), "=r"((R)[2]), "=r"((R)[3]) : "r"(addr))

#define MMA16816(D, A, b0, b1) \
    asm volatile("mma.sync.aligned.m16n8k16.row.col.f32.f16.f16.f32 " \
        "{%0,%1,%2,%3}, {%4,%5,%6,%7}, {%8,%9}, {%0,%1,%2,%3};" \
        : "+f"((D)[0]), "+f"((D)[1]), "+f"((D)[2]), "+f"((D)[3]) \
        : "r"((A)[0]), "r"((A)[1]), "r"((A)[2]), "r"((A)[3]), "r"(b0), "r"(b1))

__device__ __forceinline__ float ftanh(float x) {
    float xx = fminf(fmaxf(x, -15.f), 15.f);
    float e = __expf(2.f * xx);
    return __fdividef(e - 1.f, e + 1.f);
}

// ================= conversion kernels =================
// A[m][k] = v[b][k][s], m = b*196+s -> fp16 hi/lo
__global__ __launch_bounds__(256) void convA_kernel(const float* __restrict__ v)
{
    __shared__ float t[32][33];
    const int b  = blockIdx.z;
    const int k0 = blockIdx.x * 32;
    const int s0 = blockIdx.y * 32;
    const int tx = threadIdx.x, ty = threadIdx.y;

    #pragma unroll
    for (int i = ty; i < 32; i += 8) {
        int s = s0 + tx, k = k0 + i;
        t[i][tx] = (s < SP) ? v[((size_t)b * DVC + k) * SP + s] : 0.f;
    }
    __syncthreads();
    #pragma unroll
    for (int i = ty; i < 32; i += 8) {
        int s = s0 + i;
        if (s >= SP) continue;
        int k = k0 + tx;
        float x = t[tx][i];
        __half h = __float2half_rn(x);
        float lo = x - __half2float(h);
        size_t idx = ((size_t)(b * SP + s)) * DVC + k;
        g_Ahi[idx] = h;
        g_Alo[idx] = __float2half_rn(lo);
    }
}

__global__ __launch_bounds__(256) void convB_kernel(const float* __restrict__ W)
{
    const int k = blockIdx.y;
    const int n = blockIdx.x * 256 + threadIdx.x;
    if (n >= NPAD) return;
    float x = (n < DA) ? W[(size_t)k * DA + n] : 0.f;
    g_Bh[(size_t)k * NPAD + n] = __float2half_rn(x);
}

// ================= big GEMM via mma.sync fp16x2 (drop a*b_lo) =================
// C = Ahi*Bh + Alo*Bh (fp32 accum); epilogue: t2 = tanh(tanh(C+bv)*xq_att),
// then partial scores spart[nb][m][g] = sum_{n in block} t2 * Wa[n][g].
// tiles: BM=BN=128, BK=32, 256 thr (warps 4Mx2N), STAGES=4

#define STAGES 4
#define STAGE_BYTES 24576   // Ahi 8K | Alo 8K | Bh 8K

__global__ __launch_bounds__(256, 1) void mma_gemm_kernel(
    const float* __restrict__ bv, const float* __restrict__ Wa)
{
    extern __shared__ char smem_raw[];
    __shared__ float s_red[128][8];

    uint32_t smem_base = (uint32_t)__cvta_generic_to_shared(smem_raw);
    smem_base = (smem_base + 127u) & ~127u;

    const int tid   = threadIdx.x;
    const int lane  = tid & 31;
    const int warp  = tid >> 5;
    const int warpM = warp >> 1;
    const int warpN = warp & 1;
    const int m_blk = blockIdx.y * 128;
    const int n_blk = blockIdx.x * 128;

    // cp.async mappings (same swizzle scheme validated in R2)
    const int a_m  = tid >> 1;
    const int a_c0 = (tid & 1) * 2;
    const uint32_t a_sw0 = (uint32_t)((a_c0       ^ ((a_m >> 1) & 3)) << 4);
    const uint32_t a_sw1 = (uint32_t)(((a_c0 + 1) ^ ((a_m >> 1) & 3)) << 4);
    const int b_k  = tid >> 3;
    const int b_c0 = (tid & 7) * 2;
    const uint32_t b_sw0 = (uint32_t)((b_c0       ^ (b_k & 7)) << 4);
    const uint32_t b_sw1 = (uint32_t)(((b_c0 + 1) ^ (b_k & 7)) << 4);

    const __half* srcAhi = g_Ahi + (size_t)(m_blk + a_m) * DVC + a_c0 * 8;
    const __half* srcAlo = g_Alo + (size_t)(m_blk + a_m) * DVC + a_c0 * 8;
    const __half* srcBh  = g_Bh  + (size_t)b_k * NPAD + n_blk + b_c0 * 8;

    auto issue = [&](int kt) {
        uint32_t st = smem_base + (uint32_t)(kt % STAGES) * STAGE_BYTES;
        const __half* pa  = srcAhi + kt * 32;
        const __half* pal = srcAlo + kt * 32;
        uint32_t dA = st + a_m * 64;
        CP_ASYNC16(dA + a_sw0, pa);
        CP_ASYNC16(dA + a_sw1, pa + 8);
        uint32_t dAl = st + 8192 + a_m * 64;
        CP_ASYNC16(dAl + a_sw0, pal);
        CP_ASYNC16(dAl + a_sw1, pal + 8);
        const __half* pb = srcBh + (size_t)kt * 32 * NPAD;
        uint32_t dB = st + 16384 + b_k * 256;
        CP_ASYNC16(dB + b_sw0, pb);
        CP_ASYNC16(dB + b_sw1, pb + 8);
    };

    float acc[2][8][4];
    #pragma unroll
    for (int i = 0; i < 2; i++)
        #pragma unroll
        for (int j = 0; j < 8; j++)
            #pragma unroll
            for (int l = 0; l < 4; l++) acc[i][j][l] = 0.f;

    #pragma unroll
    for (int s = 0; s < STAGES - 1; s++) { issue(s); CP_COMMIT(); }

    const int KT = DVC / 32;   // 64
    for (int kt = 0; kt < KT; kt++) {
        CP_WAIT(STAGES - 2);
        __syncthreads();
        uint32_t st = smem_base + (uint32_t)(kt % STAGES) * STAGE_BYTES;

        #pragma unroll
        for (int ks = 0; ks < 2; ks++) {
            uint32_t ahi[2][4], alo[2][4], bh[4][4];
            #pragma unroll
            for (int mt = 0; mt < 2; mt++) {
                int row = warpM * 32 + mt * 16 + (lane & 15);
                int lc  = ks * 2 + (lane >> 4);
                uint32_t off = (uint32_t)(row * 64 + ((lc ^ ((row >> 1) & 3)) << 4));
                LDSM4(ahi[mt], st + off);
                LDSM4(alo[mt], st + 8192 + off);
            }
            #pragma unroll
            for (int nt = 0; nt < 4; nt++) {
                int row = ks * 16 + (lane & 15);
                int lc  = warpN * 8 + nt * 2 + (lane >> 4);
                uint32_t off = (uint32_t)(row * 256 + ((lc ^ (row & 7)) << 4));
                LDSM4T(bh[nt], st + 16384 + off);
            }
            if (ks == 0) {
                int nk = kt + STAGES - 1;
                if (nk < KT) issue(nk);
                CP_COMMIT();
            }
            #pragma unroll
            for (int n8 = 0; n8 < 8; n8++) {
                uint32_t b0 = bh[n8 >> 1][(n8 & 1) * 2];
                uint32_t b1 = bh[n8 >> 1][(n8 & 1) * 2 + 1];
                #pragma unroll
                for (int mt = 0; mt < 2; mt++) {
                    MMA16816(acc[mt][n8], ahi[mt], b0, b1);
                    MMA16816(acc[mt][n8], alo[mt], b0, b1);
                }
            }
        }
    }

    // ---- fused epilogue: x_att + partial scores (no g_xatt materialization) ----
    const int gq  = lane >> 2;
    const int tig = lane & 3;

    // 4 distinct rows per thread: rr = mt*2 + ihalf
    int   b_of[4];
    #pragma unroll
    for (int rr = 0; rr < 4; rr++) {
        int r = m_blk + warpM * 32 + (rr >> 1) * 16 + gq + (rr & 1) * 8;
        b_of[rr] = r / SP;
    }

    float sc[4][4];
    #pragma unroll
    for (int rr = 0; rr < 4; rr++)
        #pragma unroll
        for (int g = 0; g < 4; g++) sc[rr][g] = 0.f;

    #pragma unroll
    for (int mt = 0; mt < 2; mt++) {
        #pragma unroll
        for (int n8 = 0; n8 < 8; n8++) {
            int nbase = n_blk + warpN * 64 + n8 * 8 + tig * 2;
            #pragma unroll
            for (int i = 0; i < 4; i++) {
                int n = nbase + (i & 1);
                if (n < DA) {
                    int rr = mt * 2 + (i >> 1);
                    float x  = acc[mt][n8][i] + bv[n];
                    float t2 = ftanh(ftanh(x) * g_xq_att[(size_t)b_of[rr] * DA + n]);
                    float4 w = *reinterpret_cast<const float4*>(&Wa[n * 4]);
                    sc[rr][0] = fmaf(t2, w.x, sc[rr][0]);
                    sc[rr][1] = fmaf(t2, w.y, sc[rr][1]);
                    sc[rr][2] = fmaf(t2, w.z, sc[rr][2]);
                    sc[rr][3] = fmaf(t2, w.w, sc[rr][3]);
                }
            }
        }
    }

    // reduce across tig (lanes xor 1, 2), then across warpN via shared
    #pragma unroll
    for (int rr = 0; rr < 4; rr++)
        #pragma unroll
        for (int g = 0; g < 4; g++) {
            float v = sc[rr][g];
            v += __shfl_xor_sync(0xffffffffu, v, 1);
            v += __shfl_xor_sync(0xffffffffu, v, 2);
            sc[rr][g] = v;
        }
    if (tig == 0) {
        #pragma unroll
        for (int rr = 0; rr < 4; rr++) {
            int rl = warpM * 32 + (rr >> 1) * 16 + gq + (rr & 1) * 8;
            #pragma unroll
            for (int g = 0; g < 4; g++) s_red[rl][warpN * 4 + g] = sc[rr][g];
        }
    }
    __syncthreads();
    if (tid < 128) {
        int m = m_blk + tid;
        #pragma unroll
        for (int g = 0; g < 4; g++) {
            float v = s_red[tid][g] + s_red[tid][4 + g];
            g_spart[((size_t)blockIdx.x * MTOT + m) * 4 + g] = v;
        }
    }
}

// ================= split-K small GEMM (M=128 fixed) =================
__global__ __launch_bounds__(256) void splitk_gemm(
    const float* __restrict__ A, int lda, size_t aStrideZ,
    const float* __restrict__ B, int ldb, size_t bStrideZ,
    float* __restrict__ P, int Npad, int nOffZ, int N)
{
    __shared__ float As[16][128];
    __shared__ float Bs[16][68];
    const int tid = threadIdx.x;
    const int nb = blockIdx.x, kc = blockIdx.y, z = blockIdx.z;
    A += (size_t)z * aStrideZ;
    B += (size_t)z * bStrideZ;
    const int nbase = nb * 64;
    const int k0base = kc * 256;

    const int am  = tid & 127;
    const int acq = (tid >> 7) * 2;
    const int bkk = tid >> 4;
    const int bn4 = (tid & 15) * 4;
    const int tr = tid >> 4, tc = tid & 15;

    float acc[8][4];
    #pragma unroll
    for (int i = 0; i < 8; i++)
        #pragma unroll
        for (int j = 0; j < 4; j++) acc[i][j] = 0.f;

    for (int kt = 0; kt < 16; kt++) {
        int k0 = k0base + kt * 16;
        #pragma unroll
        for (int l = 0; l < 2; l++) {
            float4 a4 = *reinterpret_cast<const float4*>(A + (size_t)am * lda + k0 + (acq + l) * 4);
            As[(acq + l) * 4 + 0][am] = a4.x;
            As[(acq + l) * 4 + 1][am] = a4.y;
            As[(acq + l) * 4 + 2][am] = a4.z;
            As[(acq + l) * 4 + 3][am] = a4.w;
        }
        #pragma unroll
        for (int j = 0; j < 4; j++) {
            int n = nbase + bn4 + j;
            Bs[bkk][bn4 + j] = (n < N) ? B[(size_t)(k0 + bkk) * ldb + n] : 0.f;
        }
        __syncthreads();
        #pragma unroll
        for (int kk = 0; kk < 16; kk++) {
            float4 b4 = *reinterpret_cast<const float4*>(&Bs[kk][tc * 4]);
            float br[4] = {b4.x, b4.y, b4.z, b4.w};
            #pragma unroll
            for (int i = 0; i < 8; i++) {
                float a = As[kk][tr * 8 + i];
                #pragma unroll
                for (int j = 0; j < 4; j++)
                    acc[i][j] = fmaf(a, br[j], acc[i][j]);
            }
        }
        __syncthreads();
    }

    #pragma unroll
    for (int i = 0; i < 8; i++) {
        int m = tr * 8 + i;
        #pragma unroll
        for (int j = 0; j < 4; j++)
            P[((size_t)kc * 128 + m) * Npad + z * nOffZ + nbase + tc * 4 + j] = acc[i][j];
    }
}

// reduce: C[m][n] = EPI( sum_kc P + bias )
template <int EPI>
__global__ __launch_bounds__(256) void reduce_ep(
    const float* __restrict__ P, int Npad,
    const float* __restrict__ bias,
    const float* __restrict__ aux, int ldaux,
    float* __restrict__ C, int ldc, int N)
{
    int idx = blockIdx.x * 256 + threadIdx.x;
    if (idx >= 128 * N) return;
    int m = idx / N, n = idx - m * N;
    float s = bias[n];
    #pragma unroll
    for (int kc = 0; kc < 8; kc++) s += P[((size_t)kc * 128 + m) * Npad + n];
    if (EPI == 1) s = ftanh(s);
    else if (EPI == 2) s = ftanh(ftanh(s) * aux[(size_t)m * ldaux + n]);
    C[(size_t)m * ldc + n] = s;
}

// ---------------- softmax over S per (b,g); sums partial scores ----------------
__global__ __launch_bounds__(256) void softmax_kernel(const float* __restrict__ ba)
{
    const int bg = blockIdx.x;
    const int b = bg >> 2, g = bg & 3;
    const int tid = threadIdx.x;
    const int lane = tid & 31, w = tid >> 5;
    __shared__ float sh[8];

    float val = -1e30f;
    if (tid < SP) {
        int m = b * SP + tid;
        float s = ba[g];
        #pragma unroll
        for (int nb = 0; nb < NBLK; nb++)
            s += g_spart[((size_t)nb * MTOT + m) * 4 + g];
        val = s;
    }

    float v = val;
    #pragma unroll
    for (int off = 16; off > 0; off >>= 1)
        v = fmaxf(v, __shfl_xor_sync(0xffffffffu, v, off));
    if (lane == 0) sh[w] = v;
    __syncthreads();
    float mx = sh[0];
    #pragma unroll
    for (int i = 1; i < 8; i++) mx = fmaxf(mx, sh[i]);

    float e = (tid < SP) ? expf(val - mx) : 0.f;
    __syncthreads();
    float s2 = e;
    #pragma unroll
    for (int off = 16; off > 0; off >>= 1)
        s2 += __shfl_xor_sync(0xffffffffu, s2, off);
    if (lane == 0) sh[w] = s2;
    __syncthreads();
    float tot = 0.f;
    #pragma unroll
    for (int i = 0; i < 8; i++) tot += sh[i];

    if (tid < SP) g_att[(size_t)bg * SP + tid] = e / tot;
}

// ---------------- attention pooling ----------------
__global__ __launch_bounds__(128) void pool_kernel(const float* __restrict__ v)
{
    __shared__ float sv[32][197];
    __shared__ float sa[NG][SP];
    const int b = blockIdx.x;
    const int c0 = blockIdx.y * 32;
    const int tid = threadIdx.x;

    for (int i = tid; i < NG * SP; i += 128)
        sa[i / SP][i % SP] = g_att[(size_t)b * NG * SP + i];
    const float* vb = v + (size_t)b * DVC * SP + (size_t)c0 * SP;
    for (int i = tid; i < 32 * SP; i += 128)
        sv[i / SP][i % SP] = vb[i];
    __syncthreads();

    const int g = tid >> 5, ci = tid & 31;
    float acc = 0.f;
    #pragma unroll 4
    for (int s = 0; s < SP; s++)
        acc = fmaf(sa[g][s], sv[ci][s], acc);
    g_vatt[(size_t)b * NG * DVC + (size_t)g * DVC + c0 + ci] = acc;
}

// ---------------- launch ----------------
extern "C" void kernel_launch(void* const* d_in, const int* in_sizes, int n_in,
                              void* d_out, int out_size)
{
    const float* input_v = (const float*)d_in[0];
    const float* x_q     = (const float*)d_in[1];
    const float* Wv_att  = (const float*)d_in[2];
    const float* bv_att  = (const float*)d_in[3];
    const float* Wq_att  = (const float*)d_in[4];
    const float* bq_att  = (const float*)d_in[5];
    const float* Wa      = (const float*)d_in[6];
    const float* ba      = (const float*)d_in[7];
    const float* Wf      = (const float*)d_in[8];
    const float* bf      = (const float*)d_in[9];
    const float* Wqf     = (const float*)d_in[10];
    const float* bqf     = (const float*)d_in[11];
    const float* Wc      = (const float*)d_in[12];
    const float* bc      = (const float*)d_in[13];
    float* out = (float*)d_out;

    float *p_xq_att, *p_xqf, *p_vatt, *p_x, *p_part;
    cudaGetSymbolAddress((void**)&p_xq_att, g_xq_att);
    cudaGetSymbolAddress((void**)&p_xqf,    g_xqf);
    cudaGetSymbolAddress((void**)&p_vatt,   g_vatt);
    cudaGetSymbolAddress((void**)&p_x,      g_x);
    cudaGetSymbolAddress((void**)&p_part,   g_part);

    cudaFuncSetAttribute(mma_gemm_kernel,
                         cudaFuncAttributeMaxDynamicSharedMemorySize,
                         STAGES * STAGE_BYTES + 256);

    // 0) fp16 split conversions
    convB_kernel<<<dim3(NPAD / 256, DVC), 256>>>(Wv_att);
    convA_kernel<<<dim3(DVC / 32, (SP + 31) / 32, BB), dim3(32, 8)>>>(input_v);

    // 1) q projections (split-K + fused tanh reduce)
    splitk_gemm<<<dim3(19, 8, 1), 256>>>(x_q, DQ, 0, Wq_att, DA, 0, p_part, 1216, 0, DA);
    reduce_ep<1><<<(128 * DA + 255) / 256, 256>>>(p_part, 1216, bq_att, nullptr, 0,
                                                  p_xq_att, DA, DA);
    splitk_gemm<<<dim3(32, 8, 1), 256>>>(x_q, DQ, 0, Wqf, DH, 0, p_part, 2048, 0, DH);
    reduce_ep<1><<<(128 * DH + 255) / 256, 256>>>(p_part, 2048, bqf, nullptr, 0,
                                                  p_xqf, DH, DH);

    // 2) big fused GEMM (fp16x2 mma) -> partial scores only
    mma_gemm_kernel<<<dim3(NBLK, MTOT / 128), 256, STAGES * STAGE_BYTES + 256>>>(bv_att, Wa);

    // 3) softmax (sums partials)
    softmax_kernel<<<BB * NG, 256>>>(ba);

    // 4) attention pooling
    pool_kernel<<<dim3(BB, DVC / 32), 128>>>(input_v);

    // 5) glimpse fusion (batched) + fused MLB reduce
    splitk_gemm<<<dim3(8, 8, NG), 256>>>(p_vatt, NG * DVC, DVC,
                                         Wf, DHG, (size_t)DVC * DHG,
                                         p_part, 2048, DHG, DHG);
    reduce_ep<2><<<(128 * DH + 255) / 256, 256>>>(p_part, 2048, bf, p_xqf, DH,
                                                  p_x, DH, DH);

    // 6) classifier
    splitk_gemm<<<dim3(47, 8, 1), 256>>>(p_x, DH, 0, Wc, NANS, 0, p_part, 3008, 0, NANS);
    reduce_ep<0><<<(128 * NANS + 255) / 256, 256>>>(p_part, 3008, bc, nullptr, 0,
                                                    out, NANS, NANS);
}

// round 6
// speedup vs baseline: 4.3666x; 1.3823x over previous
#include <cuda_runtime.h>
#include <cuda_fp16.h>
#include <math.h>
#include <stdint.h>

#define BB   128
#define DVC  2048
#define SP   196
#define DQ   2048
#define DA   1200
#define NG   4
#define DHG  512
#define DH   2048
#define NANS 3000
#define MTOT (BB*SP)     // 25088
#define NPAD 1280
#define NBLK (NPAD/128)  // 10 n-blocks

// ---------------- scratch (static device globals) ----------------
__device__ float g_xq_att[BB*DA];
__device__ float g_xqf[BB*DH];
__device__ float g_att[BB*NG*SP];
__device__ float g_vatt[BB*NG*DVC];
__device__ float g_x[BB*DH];
__device__ float g_spart[NBLK*MTOT*NG];   // per-n-block partial scores
__device__ float g_part[8*128*3008];      // split-K partials (reused)

__device__ __half g_Ah[(size_t)MTOT*DVC];   // [m][k] fp16
__device__ __half g_Bh[(size_t)DVC*NPAD];   // [k][n] fp16, zero padded

// ---------------- PTX helpers ----------------
#define CP_ASYNC16(dst, src) \
    asm volatile("cp.async.cg.shared.global [%0], [%1], 16;\n" :: "r"(dst), "l"(src))
#define CP_COMMIT() asm volatile("cp.async.commit_group;\n")
#define CP_WAIT(n)  asm volatile("cp.async.wait_group %0;\n" :: "n"(n))

#define LDSM4(R, addr) \
    asm volatile("ldmatrix.sync.aligned.m8n8.x4.shared.b16 {%0,%1,%2,%3}, [%4];" \
        : "=r"((R)[0]), "=r"((R)[1]), "=r"((R)[2]), "=r"((R)[3]) : "r"(addr))
#define LDSM4T(R, addr) \
    asm volatile("ldmatrix.sync.aligned.m8n8.x4.trans.shared.b16 {%0,%1,%2,%3}, [%4];" \
        : "=r"((R)[0]), "=r"((R)[1]), "=r"((R)[2]), "=r"((R)[3]) : "r"(addr))

#define MMA16816(D, A, b0, b1) \
    asm volatile("mma.sync.aligned.m16n8k16.row.col.f32.f16.f16.f32 " \
        "{%0,%1,%2,%3}, {%4,%5,%6,%7}, {%8,%9}, {%0,%1,%2,%3};" \
        : "+f"((D)[0]), "+f"((D)[1]), "+f"((D)[2]), "+f"((D)[3]) \
        : "r"((A)[0]), "r"((A)[1]), "r"((A)[2]), "r"((A)[3]), "r"(b0), "r"(b1))

__device__ __forceinline__ float ftanh(float x) {
    float xx = fminf(fmaxf(x, -15.f), 15.f);
    float e = __expf(2.f * xx);
    return __fdividef(e - 1.f, e + 1.f);
}

// ================= conversion kernels =================
// A[m][k] = v[b][k][s], m = b*196+s -> fp16
__global__ __launch_bounds__(256) void convA_kernel(const float* __restrict__ v)
{
    __shared__ float t[32][33];
    const int b  = blockIdx.z;
    const int k0 = blockIdx.x * 32;
    const int s0 = blockIdx.y * 32;
    const int tx = threadIdx.x, ty = threadIdx.y;

    #pragma unroll
    for (int i = ty; i < 32; i += 8) {
        int s = s0 + tx, k = k0 + i;
        t[i][tx] = (s < SP) ? v[((size_t)b * DVC + k) * SP + s] : 0.f;
    }
    __syncthreads();
    #pragma unroll
    for (int i = ty; i < 32; i += 8) {
        int s = s0 + i;
        if (s >= SP) continue;
        int k = k0 + tx;
        g_Ah[((size_t)(b * SP + s)) * DVC + k] = __float2half_rn(t[tx][i]);
    }
}

__global__ __launch_bounds__(256) void convB_kernel(const float* __restrict__ W)
{
    const int k = blockIdx.y;
    const int n = blockIdx.x * 256 + threadIdx.x;
    if (n >= NPAD) return;
    float x = (n < DA) ? W[(size_t)k * DA + n] : 0.f;
    g_Bh[(size_t)k * NPAD + n] = __float2half_rn(x);
}

// ================= big GEMM via mma.sync fp16 single product =================
// C = Ah*Bh (fp32 accum); epilogue: t2 = tanh(tanh(C+bv)*xq_att),
// partial scores spart[nb][m][g] = sum_{n in block} t2 * Wa[n][g].
// tiles: BM=BN=128, BK=32, 256 thr (warps 4Mx2N), STAGES=4

#define STAGES 4
#define STAGE_BYTES 16384   // Ah 8K | Bh 8K

__global__ __launch_bounds__(256, 1) void mma_gemm_kernel(
    const float* __restrict__ bv, const float* __restrict__ Wa)
{
    extern __shared__ char smem_raw[];
    __shared__ float s_red[128][8];

    uint32_t smem_base = (uint32_t)__cvta_generic_to_shared(smem_raw);
    smem_base = (smem_base + 127u) & ~127u;

    const int tid   = threadIdx.x;
    const int lane  = tid & 31;
    const int warp  = tid >> 5;
    const int warpM = warp >> 1;
    const int warpN = warp & 1;
    const int m_blk = blockIdx.y * 128;
    const int n_blk = blockIdx.x * 128;

    const int a_m  = tid >> 1;
    const int a_c0 = (tid & 1) * 2;
    const uint32_t a_sw0 = (uint32_t)((a_c0       ^ ((a_m >> 1) & 3)) << 4);
    const uint32_t a_sw1 = (uint32_t)(((a_c0 + 1) ^ ((a_m >> 1) & 3)) << 4);
    const int b_k  = tid >> 3;
    const int b_c0 = (tid & 7) * 2;
    const uint32_t b_sw0 = (uint32_t)((b_c0       ^ (b_k & 7)) << 4);
    const uint32_t b_sw1 = (uint32_t)(((b_c0 + 1) ^ (b_k & 7)) << 4);

    const __half* srcA = g_Ah + (size_t)(m_blk + a_m) * DVC + a_c0 * 8;
    const __half* srcB = g_Bh + (size_t)b_k * NPAD + n_blk + b_c0 * 8;

    auto issue = [&](int kt) {
        uint32_t st = smem_base + (uint32_t)(kt % STAGES) * STAGE_BYTES;
        const __half* pa = srcA + kt * 32;
        uint32_t dA = st + a_m * 64;
        CP_ASYNC16(dA + a_sw0, pa);
        CP_ASYNC16(dA + a_sw1, pa + 8);
        const __half* pb = srcB + (size_t)kt * 32 * NPAD;
        uint32_t dB = st + 8192 + b_k * 256;
        CP_ASYNC16(dB + b_sw0, pb);
        CP_ASYNC16(dB + b_sw1, pb + 8);
    };

    float acc[2][8][4];
    #pragma unroll
    for (int i = 0; i < 2; i++)
        #pragma unroll
        for (int j = 0; j < 8; j++)
            #pragma unroll
            for (int l = 0; l < 4; l++) acc[i][j][l] = 0.f;

    #pragma unroll
    for (int s = 0; s < STAGES - 1; s++) { issue(s); CP_COMMIT(); }

    const int KT = DVC / 32;   // 64
    for (int kt = 0; kt < KT; kt++) {
        CP_WAIT(STAGES - 2);
        __syncthreads();
        uint32_t st = smem_base + (uint32_t)(kt % STAGES) * STAGE_BYTES;

        #pragma unroll
        for (int ks = 0; ks < 2; ks++) {
            uint32_t ah[2][4], bh[4][4];
            #pragma unroll
            for (int mt = 0; mt < 2; mt++) {
                int row = warpM * 32 + mt * 16 + (lane & 15);
                int lc  = ks * 2 + (lane >> 4);
                uint32_t off = (uint32_t)(row * 64 + ((lc ^ ((row >> 1) & 3)) << 4));
                LDSM4(ah[mt], st + off);
            }
            #pragma unroll
            for (int nt = 0; nt < 4; nt++) {
                int row = ks * 16 + (lane & 15);
                int lc  = warpN * 8 + nt * 2 + (lane >> 4);
                uint32_t off = (uint32_t)(row * 256 + ((lc ^ (row & 7)) << 4));
                LDSM4T(bh[nt], st + 8192 + off);
            }
            if (ks == 0) {
                int nk = kt + STAGES - 1;
                if (nk < KT) issue(nk);
                CP_COMMIT();
            }
            #pragma unroll
            for (int n8 = 0; n8 < 8; n8++) {
                uint32_t b0 = bh[n8 >> 1][(n8 & 1) * 2];
                uint32_t b1 = bh[n8 >> 1][(n8 & 1) * 2 + 1];
                #pragma unroll
                for (int mt = 0; mt < 2; mt++)
                    MMA16816(acc[mt][n8], ah[mt], b0, b1);
            }
        }
    }

    // ---- fused epilogue: x_att + partial scores ----
    const int gq  = lane >> 2;
    const int tig = lane & 3;

    int b_of[4];
    #pragma unroll
    for (int rr = 0; rr < 4; rr++) {
        int r = m_blk + warpM * 32 + (rr >> 1) * 16 + gq + (rr & 1) * 8;
        b_of[rr] = r / SP;
    }

    float sc[4][4];
    #pragma unroll
    for (int rr = 0; rr < 4; rr++)
        #pragma unroll
        for (int g = 0; g < 4; g++) sc[rr][g] = 0.f;

    #pragma unroll
    for (int mt = 0; mt < 2; mt++) {
        #pragma unroll
        for (int n8 = 0; n8 < 8; n8++) {
            int nbase = n_blk + warpN * 64 + n8 * 8 + tig * 2;
            #pragma unroll
            for (int i = 0; i < 4; i++) {
                int n = nbase + (i & 1);
                if (n < DA) {
                    int rr = mt * 2 + (i >> 1);
                    float x  = acc[mt][n8][i] + bv[n];
                    float t2 = ftanh(ftanh(x) * g_xq_att[(size_t)b_of[rr] * DA + n]);
                    float4 w = *reinterpret_cast<const float4*>(&Wa[n * 4]);
                    sc[rr][0] = fmaf(t2, w.x, sc[rr][0]);
                    sc[rr][1] = fmaf(t2, w.y, sc[rr][1]);
                    sc[rr][2] = fmaf(t2, w.z, sc[rr][2]);
                    sc[rr][3] = fmaf(t2, w.w, sc[rr][3]);
                }
            }
        }
    }

    #pragma unroll
    for (int rr = 0; rr < 4; rr++)
        #pragma unroll
        for (int g = 0; g < 4; g++) {
            float v = sc[rr][g];
            v += __shfl_xor_sync(0xffffffffu, v, 1);
            v += __shfl_xor_sync(0xffffffffu, v, 2);
            sc[rr][g] = v;
        }
    if (tig == 0) {
        #pragma unroll
        for (int rr = 0; rr < 4; rr++) {
            int rl = warpM * 32 + (rr >> 1) * 16 + gq + (rr & 1) * 8;
            #pragma unroll
            for (int g = 0; g < 4; g++) s_red[rl][warpN * 4 + g] = sc[rr][g];
        }
    }
    __syncthreads();
    if (tid < 128) {
        int m = m_blk + tid;
        #pragma unroll
        for (int g = 0; g < 4; g++) {
            float v = s_red[tid][g] + s_red[tid][4 + g];
            g_spart[((size_t)blockIdx.x * MTOT + m) * 4 + g] = v;
        }
    }
}

// ================= split-K small GEMM (M=128 fixed) =================
__global__ __launch_bounds__(256) void splitk_gemm(
    const float* __restrict__ A, int lda, size_t aStrideZ,
    const float* __restrict__ B, int ldb, size_t bStrideZ,
    float* __restrict__ P, int Npad, int nOffZ, int N)
{
    __shared__ float As[16][128];
    __shared__ float Bs[16][68];
    const int tid = threadIdx.x;
    const int nb = blockIdx.x, kc = blockIdx.y, z = blockIdx.z;
    A += (size_t)z * aStrideZ;
    B += (size_t)z * bStrideZ;
    const int nbase = nb * 64;
    const int k0base = kc * 256;

    const int am  = tid & 127;
    const int acq = (tid >> 7) * 2;
    const int bkk = tid >> 4;
    const int bn4 = (tid & 15) * 4;
    const int tr = tid >> 4, tc = tid & 15;

    float acc[8][4];
    #pragma unroll
    for (int i = 0; i < 8; i++)
        #pragma unroll
        for (int j = 0; j < 4; j++) acc[i][j] = 0.f;

    for (int kt = 0; kt < 16; kt++) {
        int k0 = k0base + kt * 16;
        #pragma unroll
        for (int l = 0; l < 2; l++) {
            float4 a4 = *reinterpret_cast<const float4*>(A + (size_t)am * lda + k0 + (acq + l) * 4);
            As[(acq + l) * 4 + 0][am] = a4.x;
            As[(acq + l) * 4 + 1][am] = a4.y;
            As[(acq + l) * 4 + 2][am] = a4.z;
            As[(acq + l) * 4 + 3][am] = a4.w;
        }
        #pragma unroll
        for (int j = 0; j < 4; j++) {
            int n = nbase + bn4 + j;
            Bs[bkk][bn4 + j] = (n < N) ? B[(size_t)(k0 + bkk) * ldb + n] : 0.f;
        }
        __syncthreads();
        #pragma unroll
        for (int kk = 0; kk < 16; kk++) {
            float4 b4 = *reinterpret_cast<const float4*>(&Bs[kk][tc * 4]);
            float br[4] = {b4.x, b4.y, b4.z, b4.w};
            #pragma unroll
            for (int i = 0; i < 8; i++) {
                float a = As[kk][tr * 8 + i];
                #pragma unroll
                for (int j = 0; j < 4; j++)
                    acc[i][j] = fmaf(a, br[j], acc[i][j]);
            }
        }
        __syncthreads();
    }

    #pragma unroll
    for (int i = 0; i < 8; i++) {
        int m = tr * 8 + i;
        #pragma unroll
        for (int j = 0; j < 4; j++)
            P[((size_t)kc * 128 + m) * Npad + z * nOffZ + nbase + tc * 4 + j] = acc[i][j];
    }
}

// reduce: C[m][n] = EPI( sum_kc P + bias )
template <int EPI>
__global__ __launch_bounds__(256) void reduce_ep(
    const float* __restrict__ P, int Npad,
    const float* __restrict__ bias,
    const float* __restrict__ aux, int ldaux,
    float* __restrict__ C, int ldc, int N)
{
    int idx = blockIdx.x * 256 + threadIdx.x;
    if (idx >= 128 * N) return;
    int m = idx / N, n = idx - m * N;
    float s = bias[n];
    #pragma unroll
    for (int kc = 0; kc < 8; kc++) s += P[((size_t)kc * 128 + m) * Npad + n];
    if (EPI == 1) s = ftanh(s);
    else if (EPI == 2) s = ftanh(ftanh(s) * aux[(size_t)m * ldaux + n]);
    C[(size_t)m * ldc + n] = s;
}

// ---------------- softmax over S per (b,g); sums partial scores ----------------
__global__ __launch_bounds__(256) void softmax_kernel(const float* __restrict__ ba)
{
    const int bg = blockIdx.x;
    const int b = bg >> 2, g = bg & 3;
    const int tid = threadIdx.x;
    const int lane = tid & 31, w = tid >> 5;
    __shared__ float sh[8];

    float val = -1e30f;
    if (tid < SP) {
        int m = b * SP + tid;
        float s = ba[g];
        #pragma unroll
        for (int nb = 0; nb < NBLK; nb++)
            s += g_spart[((size_t)nb * MTOT + m) * 4 + g];
        val = s;
    }

    float v = val;
    #pragma unroll
    for (int off = 16; off > 0; off >>= 1)
        v = fmaxf(v, __shfl_xor_sync(0xffffffffu, v, off));
    if (lane == 0) sh[w] = v;
    __syncthreads();
    float mx = sh[0];
    #pragma unroll
    for (int i = 1; i < 8; i++) mx = fmaxf(mx, sh[i]);

    float e = (tid < SP) ? expf(val - mx) : 0.f;
    __syncthreads();
    float s2 = e;
    #pragma unroll
    for (int off = 16; off > 0; off >>= 1)
        s2 += __shfl_xor_sync(0xffffffffu, s2, off);
    if (lane == 0) sh[w] = s2;
    __syncthreads();
    float tot = 0.f;
    #pragma unroll
    for (int i = 0; i < 8; i++) tot += sh[i];

    if (tid < SP) g_att[(size_t)bg * SP + tid] = e / tot;
}

// ---------------- attention pooling ----------------
__global__ __launch_bounds__(128) void pool_kernel(const float* __restrict__ v)
{
    __shared__ float sv[32][197];
    __shared__ float sa[NG][SP];
    const int b = blockIdx.x;
    const int c0 = blockIdx.y * 32;
    const int tid = threadIdx.x;

    for (int i = tid; i < NG * SP; i += 128)
        sa[i / SP][i % SP] = g_att[(size_t)b * NG * SP + i];
    const float* vb = v + (size_t)b * DVC * SP + (size_t)c0 * SP;
    for (int i = tid; i < 32 * SP; i += 128)
        sv[i / SP][i % SP] = vb[i];
    __syncthreads();

    const int g = tid >> 5, ci = tid & 31;
    float acc = 0.f;
    #pragma unroll 4
    for (int s = 0; s < SP; s++)
        acc = fmaf(sa[g][s], sv[ci][s], acc);
    g_vatt[(size_t)b * NG * DVC + (size_t)g * DVC + c0 + ci] = acc;
}

// ---------------- launch ----------------
extern "C" void kernel_launch(void* const* d_in, const int* in_sizes, int n_in,
                              void* d_out, int out_size)
{
    const float* input_v = (const float*)d_in[0];
    const float* x_q     = (const float*)d_in[1];
    const float* Wv_att  = (const float*)d_in[2];
    const float* bv_att  = (const float*)d_in[3];
    const float* Wq_att  = (const float*)d_in[4];
    const float* bq_att  = (const float*)d_in[5];
    const float* Wa      = (const float*)d_in[6];
    const float* ba      = (const float*)d_in[7];
    const float* Wf      = (const float*)d_in[8];
    const float* bf      = (const float*)d_in[9];
    const float* Wqf     = (const float*)d_in[10];
    const float* bqf     = (const float*)d_in[11];
    const float* Wc      = (const float*)d_in[12];
    const float* bc      = (const float*)d_in[13];
    float* out = (float*)d_out;

    float *p_xq_att, *p_xqf, *p_vatt, *p_x, *p_part;
    cudaGetSymbolAddress((void**)&p_xq_att, g_xq_att);
    cudaGetSymbolAddress((void**)&p_xqf,    g_xqf);
    cudaGetSymbolAddress((void**)&p_vatt,   g_vatt);
    cudaGetSymbolAddress((void**)&p_x,      g_x);
    cudaGetSymbolAddress((void**)&p_part,   g_part);

    cudaFuncSetAttribute(mma_gemm_kernel,
                         cudaFuncAttributeMaxDynamicSharedMemorySize,
                         STAGES * STAGE_BYTES + 256);

    // 0) fp16 conversions
    convB_kernel<<<dim3(NPAD / 256, DVC), 256>>>(Wv_att);
    convA_kernel<<<dim3(DVC / 32, (SP + 31) / 32, BB), dim3(32, 8)>>>(input_v);

    // 1) q projections (split-K + fused tanh reduce)
    splitk_gemm<<<dim3(19, 8, 1), 256>>>(x_q, DQ, 0, Wq_att, DA, 0, p_part, 1216, 0, DA);
    reduce_ep<1><<<(128 * DA + 255) / 256, 256>>>(p_part, 1216, bq_att, nullptr, 0,
                                                  p_xq_att, DA, DA);
    splitk_gemm<<<dim3(32, 8, 1), 256>>>(x_q, DQ, 0, Wqf, DH, 0, p_part, 2048, 0, DH);
    reduce_ep<1><<<(128 * DH + 255) / 256, 256>>>(p_part, 2048, bqf, nullptr, 0,
                                                  p_xqf, DH, DH);

    // 2) big fused GEMM (single fp16 mma product) -> partial scores
    mma_gemm_kernel<<<dim3(NBLK, MTOT / 128), 256, STAGES * STAGE_BYTES + 256>>>(bv_att, Wa);

    // 3) softmax (sums partials)
    softmax_kernel<<<BB * NG, 256>>>(ba);

    // 4) attention pooling
    pool_kernel<<<dim3(BB, DVC / 32), 128>>>(input_v);

    // 5) glimpse fusion (batched) + fused MLB reduce
    splitk_gemm<<<dim3(8, 8, NG), 256>>>(p_vatt, NG * DVC, DVC,
                                         Wf, DHG, (size_t)DVC * DHG,
                                         p_part, 2048, DHG, DHG);
    reduce_ep<2><<<(128 * DH + 255) / 256, 256>>>(p_part, 2048, bf, p_xqf, DH,
                                                  p_x, DH, DH);

    // 6) classifier
    splitk_gemm<<<dim3(47, 8, 1), 256>>>(p_x, DH, 0, Wc, NANS, 0, p_part, 3008, 0, NANS);
    reduce_ep<0><<<(128 * NANS + 255) / 256, 256>>>(p_part, 3008, bc, nullptr, 0,
                                                    out, NANS, NANS);
}

// round 7
// speedup vs baseline: 5.2291x; 1.1975x over previous
#include <cuda_runtime.h>
#include <cuda_fp16.h>
#include <math.h>
#include <stdint.h>

#define BB   128
#define DVC  2048
#define SP   196
#define DQ   2048
#define DA   1200
#define NG   4
#define DHG  512
#define DH   2048
#define NANS 3000
#define MTOT (BB*SP)     // 25088
#define NPAD 1280
#define NBLK (NPAD/128)  // 10 n-blocks

// ---------------- scratch (static device globals) ----------------
__device__ float g_xq_att[BB*DA];
__device__ float g_xqf[BB*DH];
__device__ float g_att[BB*NG*SP];
__device__ float g_vatt[BB*NG*DVC];
__device__ float g_x[BB*DH];
__device__ float g_spart[NBLK*MTOT*NG];   // per-n-block partial scores
__device__ float g_part[8*128*3008];      // split-K partials (reused)

__device__ __half g_Ah[(size_t)MTOT*DVC];   // [m][k] fp16
__device__ __half g_Bh[(size_t)DVC*NPAD];   // [k][n] fp16, zero padded

// ---------------- PTX helpers ----------------
#define CP_ASYNC16(dst, src) \
    asm volatile("cp.async.cg.shared.global [%0], [%1], 16;\n" :: "r"(dst), "l"(src))
#define CP_COMMIT() asm volatile("cp.async.commit_group;\n")
#define CP_WAIT(n)  asm volatile("cp.async.wait_group %0;\n" :: "n"(n))

#define LDSM4(R, addr) \
    asm volatile("ldmatrix.sync.aligned.m8n8.x4.shared.b16 {%0,%1,%2,%3}, [%4];" \
        : "=r"((R)[0]), "=r"((R)[1]), "=r"((R)[2]), "=r"((R)[3]) : "r"(addr))
#define LDSM4T(R, addr) \
    asm volatile("ldmatrix.sync.aligned.m8n8.x4.trans.shared.b16 {%0,%1,%2,%3}, [%4];" \
        : "=r"((R)[0]), "=r"((R)[1]), "=r"((R)[2]), "=r"((R)[3]) : "r"(addr))

#define MMA16816(D, A, b0, b1) \
    asm volatile("mma.sync.aligned.m16n8k16.row.col.f32.f16.f16.f32 " \
        "{%0,%1,%2,%3}, {%4,%5,%6,%7}, {%8,%9}, {%0,%1,%2,%3};" \
        : "+f"((D)[0]), "+f"((D)[1]), "+f"((D)[2]), "+f"((D)[3]) \
        : "r"((A)[0]), "r"((A)[1]), "r"((A)[2]), "r"((A)[3]), "r"(b0), "r"(b1))

__device__ __forceinline__ float ftanh(float x) {
    float xx = fminf(fmaxf(x, -15.f), 15.f);
    float e = __expf(2.f * xx);
    return __fdividef(e - 1.f, e + 1.f);
}

// ================= conversion kernels =================
// A[m][k] = v[b][k][s], m = b*196+s -> fp16
__global__ __launch_bounds__(256) void convA_kernel(const float* __restrict__ v)
{
    __shared__ float t[32][33];
    const int b  = blockIdx.z;
    const int k0 = blockIdx.x * 32;
    const int s0 = blockIdx.y * 32;
    const int tx = threadIdx.x, ty = threadIdx.y;

    #pragma unroll
    for (int i = ty; i < 32; i += 8) {
        int s = s0 + tx, k = k0 + i;
        t[i][tx] = (s < SP) ? v[((size_t)b * DVC + k) * SP + s] : 0.f;
    }
    __syncthreads();
    #pragma unroll
    for (int i = ty; i < 32; i += 8) {
        int s = s0 + i;
        if (s >= SP) continue;
        int k = k0 + tx;
        g_Ah[((size_t)(b * SP + s)) * DVC + k] = __float2half_rn(t[tx][i]);
    }
}

__global__ __launch_bounds__(256) void convB_kernel(const float* __restrict__ W)
{
    const int k = blockIdx.y;
    const int n = blockIdx.x * 256 + threadIdx.x;
    if (n >= NPAD) return;
    float x = (n < DA) ? W[(size_t)k * DA + n] : 0.f;
    g_Bh[(size_t)k * NPAD + n] = __float2half_rn(x);
}

// ================= big GEMM via mma.sync fp16 single product =================
// C = Ah*Bh (fp32 accum); epilogue: t2 = tanh(tanh(C+bv)*xq_att),
// partial scores spart[nb][m][g] = sum_{n in block} t2 * Wa[n][g].
// tiles: BM=BN=128, BK=32, 256 thr (warps 4Mx2N), STAGES=4, 2 CTAs/SM

#define STAGES 4
#define STAGE_BYTES 16384   // Ah 8K | Bh 8K

__global__ __launch_bounds__(256, 2) void mma_gemm_kernel(
    const float* __restrict__ bv, const float* __restrict__ Wa)
{
    extern __shared__ char smem_raw[];
    __shared__ float s_red[128][8];

    uint32_t smem_base = (uint32_t)__cvta_generic_to_shared(smem_raw);
    smem_base = (smem_base + 127u) & ~127u;

    const int tid   = threadIdx.x;
    const int lane  = tid & 31;
    const int warp  = tid >> 5;
    const int warpM = warp >> 1;
    const int warpN = warp & 1;
    const int m_blk = blockIdx.y * 128;
    const int n_blk = blockIdx.x * 128;

    const int a_m  = tid >> 1;
    const int a_c0 = (tid & 1) * 2;
    const uint32_t a_sw0 = (uint32_t)((a_c0       ^ ((a_m >> 1) & 3)) << 4);
    const uint32_t a_sw1 = (uint32_t)(((a_c0 + 1) ^ ((a_m >> 1) & 3)) << 4);
    const int b_k  = tid >> 3;
    const int b_c0 = (tid & 7) * 2;
    const uint32_t b_sw0 = (uint32_t)((b_c0       ^ (b_k & 7)) << 4);
    const uint32_t b_sw1 = (uint32_t)(((b_c0 + 1) ^ (b_k & 7)) << 4);

    const __half* srcA = g_Ah + (size_t)(m_blk + a_m) * DVC + a_c0 * 8;
    const __half* srcB = g_Bh + (size_t)b_k * NPAD + n_blk + b_c0 * 8;

    auto issue = [&](int kt) {
        uint32_t st = smem_base + (uint32_t)(kt % STAGES) * STAGE_BYTES;
        const __half* pa = srcA + kt * 32;
        uint32_t dA = st + a_m * 64;
        CP_ASYNC16(dA + a_sw0, pa);
        CP_ASYNC16(dA + a_sw1, pa + 8);
        const __half* pb = srcB + (size_t)kt * 32 * NPAD;
        uint32_t dB = st + 8192 + b_k * 256;
        CP_ASYNC16(dB + b_sw0, pb);
        CP_ASYNC16(dB + b_sw1, pb + 8);
    };

    float acc[2][8][4];
    #pragma unroll
    for (int i = 0; i < 2; i++)
        #pragma unroll
        for (int j = 0; j < 8; j++)
            #pragma unroll
            for (int l = 0; l < 4; l++) acc[i][j][l] = 0.f;

    #pragma unroll
    for (int s = 0; s < STAGES - 1; s++) { issue(s); CP_COMMIT(); }

    const int KT = DVC / 32;   // 64
    for (int kt = 0; kt < KT; kt++) {
        CP_WAIT(STAGES - 2);
        __syncthreads();
        uint32_t st = smem_base + (uint32_t)(kt % STAGES) * STAGE_BYTES;

        #pragma unroll
        for (int ks = 0; ks < 2; ks++) {
            uint32_t ah[2][4], bh[4][4];
            #pragma unroll
            for (int mt = 0; mt < 2; mt++) {
                int row = warpM * 32 + mt * 16 + (lane & 15);
                int lc  = ks * 2 + (lane >> 4);
                uint32_t off = (uint32_t)(row * 64 + ((lc ^ ((row >> 1) & 3)) << 4));
                LDSM4(ah[mt], st + off);
            }
            #pragma unroll
            for (int nt = 0; nt < 4; nt++) {
                int row = ks * 16 + (lane & 15);
                int lc  = warpN * 8 + nt * 2 + (lane >> 4);
                uint32_t off = (uint32_t)(row * 256 + ((lc ^ (row & 7)) << 4));
                LDSM4T(bh[nt], st + 8192 + off);
            }
            if (ks == 0) {
                int nk = kt + STAGES - 1;
                if (nk < KT) issue(nk);
                CP_COMMIT();
            }
            #pragma unroll
            for (int n8 = 0; n8 < 8; n8++) {
                uint32_t b0 = bh[n8 >> 1][(n8 & 1) * 2];
                uint32_t b1 = bh[n8 >> 1][(n8 & 1) * 2 + 1];
                #pragma unroll
                for (int mt = 0; mt < 2; mt++)
                    MMA16816(acc[mt][n8], ah[mt], b0, b1);
            }
        }
    }

    // ---- fused epilogue: x_att + partial scores ----
    const int gq  = lane >> 2;
    const int tig = lane & 3;

    int b_of[4];
    #pragma unroll
    for (int rr = 0; rr < 4; rr++) {
        int r = m_blk + warpM * 32 + (rr >> 1) * 16 + gq + (rr & 1) * 8;
        b_of[rr] = r / SP;
    }

    float sc[4][4];
    #pragma unroll
    for (int rr = 0; rr < 4; rr++)
        #pragma unroll
        for (int g = 0; g < 4; g++) sc[rr][g] = 0.f;

    #pragma unroll
    for (int mt = 0; mt < 2; mt++) {
        #pragma unroll
        for (int n8 = 0; n8 < 8; n8++) {
            int nbase = n_blk + warpN * 64 + n8 * 8 + tig * 2;
            #pragma unroll
            for (int i = 0; i < 4; i++) {
                int n = nbase + (i & 1);
                if (n < DA) {
                    int rr = mt * 2 + (i >> 1);
                    float x  = acc[mt][n8][i] + bv[n];
                    float t2 = ftanh(ftanh(x) * g_xq_att[(size_t)b_of[rr] * DA + n]);
                    float4 w = *reinterpret_cast<const float4*>(&Wa[n * 4]);
                    sc[rr][0] = fmaf(t2, w.x, sc[rr][0]);
                    sc[rr][1] = fmaf(t2, w.y, sc[rr][1]);
                    sc[rr][2] = fmaf(t2, w.z, sc[rr][2]);
                    sc[rr][3] = fmaf(t2, w.w, sc[rr][3]);
                }
            }
        }
    }

    #pragma unroll
    for (int rr = 0; rr < 4; rr++)
        #pragma unroll
        for (int g = 0; g < 4; g++) {
            float v = sc[rr][g];
            v += __shfl_xor_sync(0xffffffffu, v, 1);
            v += __shfl_xor_sync(0xffffffffu, v, 2);
            sc[rr][g] = v;
        }
    if (tig == 0) {
        #pragma unroll
        for (int rr = 0; rr < 4; rr++) {
            int rl = warpM * 32 + (rr >> 1) * 16 + gq + (rr & 1) * 8;
            #pragma unroll
            for (int g = 0; g < 4; g++) s_red[rl][warpN * 4 + g] = sc[rr][g];
        }
    }
    __syncthreads();
    if (tid < 128) {
        int m = m_blk + tid;
        #pragma unroll
        for (int g = 0; g < 4; g++) {
            float v = s_red[tid][g] + s_red[tid][4 + g];
            g_spart[((size_t)blockIdx.x * MTOT + m) * 4 + g] = v;
        }
    }
}

// ================= split-K small GEMM (M=128 fixed) =================
__global__ __launch_bounds__(256) void splitk_gemm(
    const float* __restrict__ A, int lda, size_t aStrideZ,
    const float* __restrict__ B, int ldb, size_t bStrideZ,
    float* __restrict__ P, int Npad, int nOffZ, int N)
{
    __shared__ float As[16][128];
    __shared__ float Bs[16][68];
    const int tid = threadIdx.x;
    const int nb = blockIdx.x, kc = blockIdx.y, z = blockIdx.z;
    A += (size_t)z * aStrideZ;
    B += (size_t)z * bStrideZ;
    const int nbase = nb * 64;
    const int k0base = kc * 256;

    const int am  = tid & 127;
    const int acq = (tid >> 7) * 2;
    const int bkk = tid >> 4;
    const int bn4 = (tid & 15) * 4;
    const int tr = tid >> 4, tc = tid & 15;

    float acc[8][4];
    #pragma unroll
    for (int i = 0; i < 8; i++)
        #pragma unroll
        for (int j = 0; j < 4; j++) acc[i][j] = 0.f;

    for (int kt = 0; kt < 16; kt++) {
        int k0 = k0base + kt * 16;
        #pragma unroll
        for (int l = 0; l < 2; l++) {
            float4 a4 = *reinterpret_cast<const float4*>(A + (size_t)am * lda + k0 + (acq + l) * 4);
            As[(acq + l) * 4 + 0][am] = a4.x;
            As[(acq + l) * 4 + 1][am] = a4.y;
            As[(acq + l) * 4 + 2][am] = a4.z;
            As[(acq + l) * 4 + 3][am] = a4.w;
        }
        #pragma unroll
        for (int j = 0; j < 4; j++) {
            int n = nbase + bn4 + j;
            Bs[bkk][bn4 + j] = (n < N) ? B[(size_t)(k0 + bkk) * ldb + n] : 0.f;
        }
        __syncthreads();
        #pragma unroll
        for (int kk = 0; kk < 16; kk++) {
            float4 b4 = *reinterpret_cast<const float4*>(&Bs[kk][tc * 4]);
            float br[4] = {b4.x, b4.y, b4.z, b4.w};
            #pragma unroll
            for (int i = 0; i < 8; i++) {
                float a = As[kk][tr * 8 + i];
                #pragma unroll
                for (int j = 0; j < 4; j++)
                    acc[i][j] = fmaf(a, br[j], acc[i][j]);
            }
        }
        __syncthreads();
    }

    #pragma unroll
    for (int i = 0; i < 8; i++) {
        int m = tr * 8 + i;
        #pragma unroll
        for (int j = 0; j < 4; j++)
            P[((size_t)kc * 128 + m) * Npad + z * nOffZ + nbase + tc * 4 + j] = acc[i][j];
    }
}

// reduce: C[m][n] = EPI( sum_kc P + bias )
template <int EPI>
__global__ __launch_bounds__(256) void reduce_ep(
    const float* __restrict__ P, int Npad,
    const float* __restrict__ bias,
    const float* __restrict__ aux, int ldaux,
    float* __restrict__ C, int ldc, int N)
{
    int idx = blockIdx.x * 256 + threadIdx.x;
    if (idx >= 128 * N) return;
    int m = idx / N, n = idx - m * N;
    float s = bias[n];
    #pragma unroll
    for (int kc = 0; kc < 8; kc++) s += P[((size_t)kc * 128 + m) * Npad + n];
    if (EPI == 1) s = ftanh(s);
    else if (EPI == 2) s = ftanh(ftanh(s) * aux[(size_t)m * ldaux + n]);
    C[(size_t)m * ldc + n] = s;
}

// ---------------- softmax over S per (b,g); sums partial scores ----------------
__global__ __launch_bounds__(256) void softmax_kernel(const float* __restrict__ ba)
{
    const int bg = blockIdx.x;
    const int b = bg >> 2, g = bg & 3;
    const int tid = threadIdx.x;
    const int lane = tid & 31, w = tid >> 5;
    __shared__ float sh[8];

    float val = -1e30f;
    if (tid < SP) {
        int m = b * SP + tid;
        float s = ba[g];
        #pragma unroll
        for (int nb = 0; nb < NBLK; nb++)
            s += g_spart[((size_t)nb * MTOT + m) * 4 + g];
        val = s;
    }

    float v = val;
    #pragma unroll
    for (int off = 16; off > 0; off >>= 1)
        v = fmaxf(v, __shfl_xor_sync(0xffffffffu, v, off));
    if (lane == 0) sh[w] = v;
    __syncthreads();
    float mx = sh[0];
    #pragma unroll
    for (int i = 1; i < 8; i++) mx = fmaxf(mx, sh[i]);

    float e = (tid < SP) ? expf(val - mx) : 0.f;
    __syncthreads();
    float s2 = e;
    #pragma unroll
    for (int off = 16; off > 0; off >>= 1)
        s2 += __shfl_xor_sync(0xffffffffu, s2, off);
    if (lane == 0) sh[w] = s2;
    __syncthreads();
    float tot = 0.f;
    #pragma unroll
    for (int i = 0; i < 8; i++) tot += sh[i];

    if (tid < SP) g_att[(size_t)bg * SP + tid] = e / tot;
}

// ---------------- attention pooling ----------------
__global__ __launch_bounds__(128) void pool_kernel(const float* __restrict__ v)
{
    __shared__ float sv[32][197];
    __shared__ float sa[NG][SP];
    const int b = blockIdx.x;
    const int c0 = blockIdx.y * 32;
    const int tid = threadIdx.x;

    for (int i = tid; i < NG * SP; i += 128)
        sa[i / SP][i % SP] = g_att[(size_t)b * NG * SP + i];
    const float* vb = v + (size_t)b * DVC * SP + (size_t)c0 * SP;
    for (int i = tid; i < 32 * SP; i += 128)
        sv[i / SP][i % SP] = vb[i];
    __syncthreads();

    const int g = tid >> 5, ci = tid & 31;
    float acc = 0.f;
    #pragma unroll 4
    for (int s = 0; s < SP; s++)
        acc = fmaf(sa[g][s], sv[ci][s], acc);
    g_vatt[(size_t)b * NG * DVC + (size_t)g * DVC + c0 + ci] = acc;
}

// ---------------- launch ----------------
extern "C" void kernel_launch(void* const* d_in, const int* in_sizes, int n_in,
                              void* d_out, int out_size)
{
    const float* input_v = (const float*)d_in[0];
    const float* x_q     = (const float*)d_in[1];
    const float* Wv_att  = (const float*)d_in[2];
    const float* bv_att  = (const float*)d_in[3];
    const float* Wq_att  = (const float*)d_in[4];
    const float* bq_att  = (const float*)d_in[5];
    const float* Wa      = (const float*)d_in[6];
    const float* ba      = (const float*)d_in[7];
    const float* Wf      = (const float*)d_in[8];
    const float* bf      = (const float*)d_in[9];
    const float* Wqf     = (const float*)d_in[10];
    const float* bqf     = (const float*)d_in[11];
    const float* Wc      = (const float*)d_in[12];
    const float* bc      = (const float*)d_in[13];
    float* out = (float*)d_out;

    float *p_xq_att, *p_xqf, *p_vatt, *p_x, *p_part;
    cudaGetSymbolAddress((void**)&p_xq_att, g_xq_att);
    cudaGetSymbolAddress((void**)&p_xqf,    g_xqf);
    cudaGetSymbolAddress((void**)&p_vatt,   g_vatt);
    cudaGetSymbolAddress((void**)&p_x,      g_x);
    cudaGetSymbolAddress((void**)&p_part,   g_part);

    cudaFuncSetAttribute(mma_gemm_kernel,
                         cudaFuncAttributeMaxDynamicSharedMemorySize,
                         STAGES * STAGE_BYTES + 256);

    // 0) fp16 conversions
    convB_kernel<<<dim3(NPAD / 256, DVC), 256>>>(Wv_att);
    convA_kernel<<<dim3(DVC / 32, (SP + 31) / 32, BB), dim3(32, 8)>>>(input_v);

    // 1) q projections (split-K + fused tanh reduce)
    splitk_gemm<<<dim3(19, 8, 1), 256>>>(x_q, DQ, 0, Wq_att, DA, 0, p_part, 1216, 0, DA);
    reduce_ep<1><<<(128 * DA + 255) / 256, 256>>>(p_part, 1216, bq_att, nullptr, 0,
                                                  p_xq_att, DA, DA);
    splitk_gemm<<<dim3(32, 8, 1), 256>>>(x_q, DQ, 0, Wqf, DH, 0, p_part, 2048, 0, DH);
    reduce_ep<1><<<(128 * DH + 255) / 256, 256>>>(p_part, 2048, bqf, nullptr, 0,
                                                  p_xqf, DH, DH);

    // 2) big fused GEMM (single fp16 mma product, 2 CTAs/SM) -> partial scores
    mma_gemm_kernel<<<dim3(NBLK, MTOT / 128), 256, STAGES * STAGE_BYTES + 256>>>(bv_att, Wa);

    // 3) softmax (sums partials)
    softmax_kernel<<<BB * NG, 256>>>(ba);

    // 4) attention pooling
    pool_kernel<<<dim3(BB, DVC / 32), 128>>>(input_v);

    // 5) glimpse fusion (batched) + fused MLB reduce
    splitk_gemm<<<dim3(8, 8, NG), 256>>>(p_vatt, NG * DVC, DVC,
                                         Wf, DHG, (size_t)DVC * DHG,
                                         p_part, 2048, DHG, DHG);
    reduce_ep<2><<<(128 * DH + 255) / 256, 256>>>(p_part, 2048, bf, p_xqf, DH,
                                                  p_x, DH, DH);

    // 6) classifier
    splitk_gemm<<<dim3(47, 8, 1), 256>>>(p_x, DH, 0, Wc, NANS, 0, p_part, 3008, 0, NANS);
    reduce_ep<0><<<(128 * NANS + 255) / 256, 256>>>(p_part, 3008, bc, nullptr, 0,
                                                    out, NANS, NANS);
}